// round 17
// baseline (speedup 1.0000x reference)
#include <cuda_runtime.h>

#define NN   50000
#define FIN  128
#define HID  16
#define EMAX 800000

// Scratch — referenced ONLY inside kernel bodies (never as host-side args!)
// g_cnt is self-restoring: zero at module load; k_out's tail re-zeroes it.
static __device__ int   g_cnt [NN];
static __device__ float g_dinv[NN];
static __device__ float g_h1s [NN * HID];   // (x@W1) * dinv[node]
static __device__ float g_agg1[NN * HID];
static __device__ float g_h2s [NN * HID];   // relu(...) * dinv[node]
static __device__ float g_agg2[NN * HID];

// ---------------------------------------------------------------------------
__device__ __forceinline__ void red_add_v4(float* addr, float4 v) {
    asm volatile("red.global.add.v4.f32 [%0], {%1, %2, %3, %4};"
                 :: "l"(addr), "f"(v.x), "f"(v.y), "f"(v.z), "f"(v.w)
                 : "memory");
}

// ---------------------------------------------------------------------------
// 1) in-degree histogram over dst (row 1 of int32 [2,E]) — 4 edges/thread
__global__ void k_deg(const int* __restrict__ ei) {
    int t = blockIdx.x * blockDim.x + threadIdx.x;
    if (t >= EMAX / 4) return;
    int4 d4 = __ldg((const int4*)(ei + EMAX) + t);
    atomicAdd(&g_cnt[d4.x], 1);
    atomicAdd(&g_cnt[d4.y], 1);
    atomicAdd(&g_cnt[d4.z], 1);
    atomicAdd(&g_cnt[d4.w], 1);
}

// ---------------------------------------------------------------------------
// 2) h1s = (x @ W1) * dinv, dinv = rsqrt(1+cnt); zeroes this tile's agg rows.
#define XS_STRIDE 132
__global__ __launch_bounds__(256) void k_mm1(const float* __restrict__ x,
                                             const float* __restrict__ W1) {
    __shared__ float xs[32 * XS_STRIDE];  // 16.5 KB
    __shared__ float ws[FIN * HID];       // 8 KB
    __shared__ float dvs[32];
    int node0 = blockIdx.x * 32;
    int tid = threadIdx.x;

    {   // zero agg1/agg2 rows of this tile
        size_t base4 = (size_t)node0 * HID / 4;
        size_t lim4  = (size_t)NN * HID / 4;
        if (tid < 128) {
            size_t idx = base4 + tid;
            if (idx < lim4) ((float4*)g_agg1)[idx] = make_float4(0.f, 0.f, 0.f, 0.f);
        } else {
            size_t idx = base4 + (tid - 128);
            if (idx < lim4) ((float4*)g_agg2)[idx] = make_float4(0.f, 0.f, 0.f, 0.f);
        }
    }
    for (int i4 = tid; i4 < FIN * HID / 4; i4 += 256)
        ((float4*)ws)[i4] = __ldg((const float4*)W1 + i4);
    for (int i4 = tid; i4 < 32 * FIN / 4; i4 += 256) {
        int row = i4 >> 5, col4 = i4 & 31;
        int node = node0 + row;
        float4 v = (node < NN) ? __ldg((const float4*)(x + (size_t)node * FIN) + col4)
                               : make_float4(0.f, 0.f, 0.f, 0.f);
        *(float4*)&xs[row * XS_STRIDE + col4 * 4] = v;
    }
    if (tid < 32) {
        int node = node0 + tid;
        float d = (node < NN) ? rsqrtf(1.0f + (float)g_cnt[node]) : 0.f;
        dvs[tid] = d;
        if (node < NN) g_dinv[node] = d;
    }
    __syncthreads();

    int n = tid >> 3, og = tid & 7;
    int o0 = og * 2;
    float acc0 = 0.f, acc1 = 0.f;
    #pragma unroll
    for (int k4 = 0; k4 < FIN / 4; k4++) {
        float4 xv = *(const float4*)&xs[n * XS_STRIDE + k4 * 4];
        float2 w0 = *(const float2*)&ws[(k4 * 4 + 0) * HID + o0];
        float2 w1 = *(const float2*)&ws[(k4 * 4 + 1) * HID + o0];
        float2 w2 = *(const float2*)&ws[(k4 * 4 + 2) * HID + o0];
        float2 w3 = *(const float2*)&ws[(k4 * 4 + 3) * HID + o0];
        acc0 += xv.x * w0.x + xv.y * w1.x + xv.z * w2.x + xv.w * w3.x;
        acc1 += xv.x * w0.y + xv.y * w1.y + xv.z * w2.y + xv.w * w3.y;
    }
    int node = node0 + n;
    if (node < NN) {
        float dv = dvs[n];
        g_h1s[node * HID + o0]     = acc0 * dv;
        g_h1s[node * HID + o0 + 1] = acc1 * dv;
    }
}

// ---------------------------------------------------------------------------
// 3/5) scatter: agg[dst] += h[src] — 16 edges per 4-thread group,
//      software-pipelined 8+8; thread q owns feature quarter q.
__device__ __forceinline__ void scat_body(const int* __restrict__ ei,
                                          const float* __restrict__ h,
                                          float* __restrict__ agg) {
    int t = blockIdx.x * blockDim.x + threadIdx.x;
    int q = t & 3;
    int g = t >> 2;                              // 16-edge group
    if (g >= EMAX / 16) return;
    const int4* s4p = (const int4*)ei + g * 4;
    const int4* d4p = (const int4*)(ei + EMAX) + g * 4;

    // batch A (edges 0-7)
    int4 sa = __ldg(s4p),     sb = __ldg(s4p + 1);
    int4 da = __ldg(d4p),     db = __ldg(d4p + 1);
    float4 a0 = ((const float4*)(h + (size_t)sa.x * HID))[q];
    float4 a1 = ((const float4*)(h + (size_t)sa.y * HID))[q];
    float4 a2 = ((const float4*)(h + (size_t)sa.z * HID))[q];
    float4 a3 = ((const float4*)(h + (size_t)sa.w * HID))[q];
    float4 a4 = ((const float4*)(h + (size_t)sb.x * HID))[q];
    float4 a5 = ((const float4*)(h + (size_t)sb.y * HID))[q];
    float4 a6 = ((const float4*)(h + (size_t)sb.z * HID))[q];
    float4 a7 = ((const float4*)(h + (size_t)sb.w * HID))[q];
    // batch B indices + gathers issued before A's reds (keep MLP high)
    int4 sc = __ldg(s4p + 2), sd = __ldg(s4p + 3);
    int4 dc = __ldg(d4p + 2), dd = __ldg(d4p + 3);
    float4 b0 = ((const float4*)(h + (size_t)sc.x * HID))[q];
    float4 b1 = ((const float4*)(h + (size_t)sc.y * HID))[q];
    float4 b2 = ((const float4*)(h + (size_t)sc.z * HID))[q];
    float4 b3 = ((const float4*)(h + (size_t)sc.w * HID))[q];
    red_add_v4((float*)((float4*)(agg + (size_t)da.x * HID) + q), a0);
    red_add_v4((float*)((float4*)(agg + (size_t)da.y * HID) + q), a1);
    red_add_v4((float*)((float4*)(agg + (size_t)da.z * HID) + q), a2);
    red_add_v4((float*)((float4*)(agg + (size_t)da.w * HID) + q), a3);
    float4 b4 = ((const float4*)(h + (size_t)sd.x * HID))[q];
    float4 b5 = ((const float4*)(h + (size_t)sd.y * HID))[q];
    float4 b6 = ((const float4*)(h + (size_t)sd.z * HID))[q];
    float4 b7 = ((const float4*)(h + (size_t)sd.w * HID))[q];
    red_add_v4((float*)((float4*)(agg + (size_t)db.x * HID) + q), a4);
    red_add_v4((float*)((float4*)(agg + (size_t)db.y * HID) + q), a5);
    red_add_v4((float*)((float4*)(agg + (size_t)db.z * HID) + q), a6);
    red_add_v4((float*)((float4*)(agg + (size_t)db.w * HID) + q), a7);
    red_add_v4((float*)((float4*)(agg + (size_t)dc.x * HID) + q), b0);
    red_add_v4((float*)((float4*)(agg + (size_t)dc.y * HID) + q), b1);
    red_add_v4((float*)((float4*)(agg + (size_t)dc.z * HID) + q), b2);
    red_add_v4((float*)((float4*)(agg + (size_t)dc.w * HID) + q), b3);
    red_add_v4((float*)((float4*)(agg + (size_t)dd.x * HID) + q), b4);
    red_add_v4((float*)((float4*)(agg + (size_t)dd.y * HID) + q), b5);
    red_add_v4((float*)((float4*)(agg + (size_t)dd.z * HID) + q), b6);
    red_add_v4((float*)((float4*)(agg + (size_t)dd.w * HID) + q), b7);
}

__global__ void k_scat1(const int* __restrict__ ei) { scat_body(ei, g_h1s, g_agg1); }
__global__ void k_scat2(const int* __restrict__ ei) { scat_body(ei, g_h2s, g_agg2); }

// ---------------------------------------------------------------------------
// 4) h2s = relu(dinv*(agg1 + h1s) + b1) * dinv — two float4 per thread
__global__ void k_relu(const float* __restrict__ b1) {
    int t = blockIdx.x * blockDim.x + threadIdx.x;
    if (t >= NN * HID / 8) return;
    int i0 = t * 2;                      // two f4 slots, same node
    int node = i0 >> 2;
    float di = g_dinv[node];
    float4 aA = ((const float4*)g_agg1)[i0];
    float4 hA = ((const float4*)g_h1s)[i0];
    float4 aB = ((const float4*)g_agg1)[i0 + 1];
    float4 hB = ((const float4*)g_h1s)[i0 + 1];
    float4 bA = __ldg((const float4*)b1 + (i0 & 3));
    float4 bB = __ldg((const float4*)b1 + ((i0 + 1) & 3));
    float4 rA, rB;
    rA.x = fmaxf(di * (aA.x + hA.x) + bA.x, 0.f) * di;
    rA.y = fmaxf(di * (aA.y + hA.y) + bA.y, 0.f) * di;
    rA.z = fmaxf(di * (aA.z + hA.z) + bA.z, 0.f) * di;
    rA.w = fmaxf(di * (aA.w + hA.w) + bA.w, 0.f) * di;
    rB.x = fmaxf(di * (aB.x + hB.x) + bB.x, 0.f) * di;
    rB.y = fmaxf(di * (aB.y + hB.y) + bB.y, 0.f) * di;
    rB.z = fmaxf(di * (aB.z + hB.z) + bB.z, 0.f) * di;
    rB.w = fmaxf(di * (aB.w + hB.w) + bB.w, 0.f) * di;
    ((float4*)g_h2s)[i0]     = rA;
    ((float4*)g_h2s)[i0 + 1] = rB;
}

// ---------------------------------------------------------------------------
// 6) out = (dinv*(agg2 + h2s)) @ W2 + b2 — 64 nodes / 512-thread block.
//    Streaming stores (__stwt): keep x/ei resident in L2 for next replay.
//    Tail: zero g_cnt rows for the next invocation.
#define VS_STRIDE 17
__global__ __launch_bounds__(512) void k_out(const float* __restrict__ W2,
                                             const float* __restrict__ b2,
                                             float* __restrict__ out) {
    __shared__ float wsh[HID * FIN];
    __shared__ float vsh[64 * VS_STRIDE];
    __shared__ float b2s[FIN];
    int node0 = blockIdx.x * 64;
    int tid = threadIdx.x;

    for (int i4 = tid; i4 < HID * FIN / 4; i4 += 512)
        ((float4*)wsh)[i4] = __ldg((const float4*)W2 + i4);
    if (tid < FIN) b2s[tid] = __ldg(&b2[tid]);
    for (int i = tid; i < 64 * HID; i += 512) {
        int nl = i >> 4, f = i & 15;
        int node = node0 + nl;
        float v = 0.f;
        if (node < NN) {
            int gi = node * HID + f;
            v = g_dinv[node] * (g_agg2[gi] + g_h2s[gi]);
        }
        vsh[nl * VS_STRIDE + f] = v;
    }
    if (tid < 64) {
        int node = node0 + tid;
        if (node < NN) g_cnt[node] = 0;
    }
    __syncthreads();

    int n = tid >> 3, og = tid & 7;
    int node = node0 + n;
    if (node >= NN) return;

    float acc[4][4];
    #pragma unroll
    for (int j = 0; j < 4; j++)
        #pragma unroll
        for (int i = 0; i < 4; i++)
            acc[j][i] = b2s[og * 4 + 32 * j + i];

    #pragma unroll
    for (int k = 0; k < HID; k++) {
        float v = vsh[n * VS_STRIDE + k];
        #pragma unroll
        for (int j = 0; j < 4; j++) {
            float4 w = *(const float4*)&wsh[k * FIN + og * 4 + 32 * j];
            acc[j][0] += v * w.x;  acc[j][1] += v * w.y;
            acc[j][2] += v * w.z;  acc[j][3] += v * w.w;
        }
    }
    float* orow = out + (size_t)node * FIN;
    #pragma unroll
    for (int j = 0; j < 4; j++)
        __stwt((float4*)&orow[og * 4 + 32 * j],
               make_float4(acc[j][0], acc[j][1], acc[j][2], acc[j][3]));
}

// ---------------------------------------------------------------------------
extern "C" void kernel_launch(void* const* d_in, const int* in_sizes, int n_in,
                              void* d_out, int out_size) {
    // Binding proven in R9: 0:x  1:edge_index(int32 [2,E])  2:W1  3:b1  4:W2  5:b2
    const float* x  = (const float*)d_in[0];
    const int*   ei = (const int*)d_in[1];
    const float* W1 = (const float*)d_in[2];
    const float* b1 = (const float*)d_in[3];
    const float* W2 = (const float*)d_in[4];
    const float* b2 = (const float*)d_in[5];
    float* out = (float*)d_out;

    k_deg  <<<(EMAX / 4 + 255) / 256, 256>>>(ei);
    k_mm1  <<<(NN + 31) / 32, 256>>>(x, W1);
    k_scat1<<<(EMAX / 4 + 255) / 256, 256>>>(ei);
    k_relu <<<(NN * HID / 8 + 255) / 256, 256>>>(b1);
    k_scat2<<<(EMAX / 4 + 255) / 256, 256>>>(ei);
    k_out  <<<(NN + 63) / 64, 512>>>(W2, b2, out);
}